// round 7
// baseline (speedup 1.0000x reference)
#include <cuda_runtime.h>
#include <cuda_bf16.h>
#include <cstdint>

#define N_NODES 50000
#define N_EDGES 625000
#define IN_DIM  512
#define HID     128
#define OUT_DIM 40
#define N_LAYERS 3
#define NB_SCAN ((N_NODES + 1023) / 1024)
#define N_TILES ((N_NODES + 127) / 128)

// ---------------- scratch ---------------------------------------------------
__device__ float g_h[N_NODES * HID];
__device__ float g_z[N_NODES * HID];
__device__ int   g_deg[N_NODES];
__device__ int   g_off[N_NODES];
__device__ int   g_cur[N_NODES];
__device__ uint2 g_edge[N_EDGES];          // {src, w_bits}
__device__ int   g_bsum[64];
__device__ uint32_t g_eBh[HID * (IN_DIM / 2)];
__device__ uint32_t g_eBl[HID * (IN_DIM / 2)];
__device__ uint32_t g_W1h[N_LAYERS * HID * (HID / 2)];
__device__ uint32_t g_W1l[N_LAYERS * HID * (HID / 2)];
__device__ uint32_t g_W2h[N_LAYERS * HID * (HID / 2)];
__device__ uint32_t g_W2l[N_LAYERS * HID * (HID / 2)];

// ---------------- helpers ----------------------------------------------------
__device__ __forceinline__ void split2(float v0, float v1, uint32_t& hi, uint32_t& lo) {
    uint16_t h0, h1, l0, l1;
    asm("cvt.rn.bf16.f32 %0, %1;" : "=h"(h0) : "f"(v0));
    asm("cvt.rn.bf16.f32 %0, %1;" : "=h"(h1) : "f"(v1));
    float r0 = v0 - __uint_as_float((uint32_t)h0 << 16);
    float r1 = v1 - __uint_as_float((uint32_t)h1 << 16);
    asm("cvt.rn.bf16.f32 %0, %1;" : "=h"(l0) : "f"(r0));
    asm("cvt.rn.bf16.f32 %0, %1;" : "=h"(l1) : "f"(r1));
    hi = ((uint32_t)h1 << 16) | h0;
    lo = ((uint32_t)l1 << 16) | l0;
}
__device__ __forceinline__ void mma_bf16(float* c, uint32_t a0, uint32_t a1,
                                         uint32_t a2, uint32_t a3,
                                         uint32_t b0, uint32_t b1) {
    asm volatile("mma.sync.aligned.m16n8k16.row.col.f32.bf16.bf16.f32 "
                 "{%0,%1,%2,%3}, {%4,%5,%6,%7}, {%8,%9}, {%0,%1,%2,%3};"
                 : "+f"(c[0]), "+f"(c[1]), "+f"(c[2]), "+f"(c[3])
                 : "r"(a0), "r"(a1), "r"(a2), "r"(a3), "r"(b0), "r"(b1));
}

// ---------------- CSR build -------------------------------------------------
__global__ void zero_deg_kernel() {
    int i = blockIdx.x * blockDim.x + threadIdx.x;
    if (i < N_NODES) g_deg[i] = 0;
}
__global__ void hist_kernel(const int* __restrict__ dst) {
    int e = blockIdx.x * blockDim.x + threadIdx.x;
    if (e < N_EDGES) atomicAdd(&g_deg[dst[e]], 1);
}
__global__ void scan1_kernel() {
    __shared__ int s[1024];
    int t = threadIdx.x;
    int i = blockIdx.x * 1024 + t;
    int v = (i < N_NODES) ? g_deg[i] : 0;
    s[t] = v;
    __syncthreads();
    for (int d = 1; d < 1024; d <<= 1) {
        int tmp = (t >= d) ? s[t - d] : 0;
        __syncthreads();
        s[t] += tmp;
        __syncthreads();
    }
    if (i < N_NODES) g_off[i] = s[t] - v;
    if (t == 1023) g_bsum[blockIdx.x] = s[1023];
}
__global__ void scan23_kernel() {
    __shared__ int red[64];
    __shared__ int base_s;
    int t = threadIdx.x;
    if (t < 64) red[t] = (t < NB_SCAN && t < (int)blockIdx.x) ? g_bsum[t] : 0;
    __syncthreads();
    if (t < 32) {
        int s = red[t] + red[t + 32];
        for (int d = 16; d > 0; d >>= 1) s += __shfl_down_sync(0xffffffffu, s, d);
        if (t == 0) base_s = s;
    }
    __syncthreads();
    int i = blockIdx.x * 1024 + t;
    if (i < N_NODES) {
        int o = g_off[i] + base_s;
        g_off[i] = o;
        g_cur[i] = o;
    }
}
__global__ void scatter_kernel(const int* __restrict__ src,
                               const int* __restrict__ dst,
                               const float* __restrict__ ew) {
    int e = blockIdx.x * blockDim.x + threadIdx.x;
    if (e < N_EDGES) {
        int d = dst[e];
        int pos = atomicAdd(&g_cur[d], 1);
        g_edge[pos] = make_uint2((uint32_t)src[e], __float_as_uint(ew[e]));
    }
}

// ---------------- weight prep ------------------------------------------------
__global__ void prep_emb_kernel(const float* __restrict__ W) {
    int idx = blockIdx.x * blockDim.x + threadIdx.x;
    int n = idx >> 8, k2 = idx & 255;
    uint32_t hi, lo;
    split2(W[(size_t)(2 * k2) * HID + n], W[(size_t)(2 * k2 + 1) * HID + n], hi, lo);
    g_eBh[n * 256 + k2] = hi;
    g_eBl[n * 256 + k2] = lo;
}
__global__ void prep_w_kernel(const float* __restrict__ W1, const float* __restrict__ W2) {
    int idx = blockIdx.x * blockDim.x + threadIdx.x;
    if (idx >= N_LAYERS * HID * 64) return;
    int l = idx / (HID * 64);
    int rem = idx - l * HID * 64;
    int n = rem >> 6, k2 = rem & 63;
    const float* w1 = W1 + (size_t)l * HID * HID;
    const float* w2 = W2 + (size_t)l * HID * HID;
    uint32_t hi, lo;
    split2(w1[(2 * k2) * HID + n], w1[(2 * k2 + 1) * HID + n], hi, lo);
    g_W1h[idx] = hi; g_W1l[idx] = lo;
    split2(w2[(2 * k2) * HID + n], w2[(2 * k2 + 1) * HID + n], hi, lo);
    g_W2h[idx] = hi; g_W2l[idx] = lo;
}

// ---------------- emb GEMM: 512 threads, 16 warps of 16x64 ------------------
#define ST 36
__global__ void __launch_bounds__(512, 1)
emb_gemm_kernel(const float* __restrict__ A, const float* __restrict__ bias, int M) {
    extern __shared__ uint32_t sh[];
    uint32_t* Ah = sh;
    uint32_t* Al = sh + 128 * ST;
    uint32_t* Bh = sh + 2 * 128 * ST;
    uint32_t* Bl = sh + 3 * 128 * ST;

    const int tid = threadIdx.x, lane = tid & 31, wid = tid >> 5;
    const int g = lane >> 2, tg = lane & 3;
    const int wm = wid & 7, wn = wid >> 3;     // 8 x 2 warps
    const int row0 = blockIdx.x * 128;

    float4 aR[4];
    uint4  bRh[2], bRl[2];

#pragma unroll
    for (int it = 0; it < 4; it++) {
        int e = tid + it * 512;                // 2048 float4 slots
        int m = e >> 4, j = e & 15;
        int r = row0 + m;
        aR[it] = make_float4(0.f, 0.f, 0.f, 0.f);
        if (r < M) aR[it] = *(const float4*)(A + (size_t)r * IN_DIM + j * 4);
    }
#pragma unroll
    for (int it = 0; it < 2; it++) {
        int e = tid + it * 512;                // 1024 uint4 slots
        int n = e >> 3, q = e & 7;
        bRh[it] = *(const uint4*)(g_eBh + n * 256 + q * 4);
        bRl[it] = *(const uint4*)(g_eBl + n * 256 + q * 4);
    }

    float c[8][4];
#pragma unroll
    for (int ni = 0; ni < 8; ni++)
#pragma unroll
        for (int q = 0; q < 4; q++) c[ni][q] = 0.f;

    for (int kc = 0; kc < IN_DIM; kc += 64) {
#pragma unroll
        for (int it = 0; it < 4; it++) {
            int e = tid + it * 512;
            int m = e >> 4, j = e & 15;
            uint32_t h0, l0, h1, l1;
            split2(aR[it].x, aR[it].y, h0, l0);
            split2(aR[it].z, aR[it].w, h1, l1);
            int o = m * ST + j * 2;
            Ah[o] = h0; Ah[o + 1] = h1;
            Al[o] = l0; Al[o + 1] = l1;
        }
#pragma unroll
        for (int it = 0; it < 2; it++) {
            int e = tid + it * 512;
            int n = e >> 3, q = e & 7;
            int o = n * ST + q * 4;
            *(uint4*)(Bh + o) = bRh[it];
            *(uint4*)(Bl + o) = bRl[it];
        }
        __syncthreads();

        if (kc + 64 < IN_DIM) {
            int kn = kc + 64, kn2 = kn >> 1;
#pragma unroll
            for (int it = 0; it < 4; it++) {
                int e = tid + it * 512;
                int m = e >> 4, j = e & 15;
                int r = row0 + m;
                aR[it] = make_float4(0.f, 0.f, 0.f, 0.f);
                if (r < M) aR[it] = *(const float4*)(A + (size_t)r * IN_DIM + kn + j * 4);
            }
#pragma unroll
            for (int it = 0; it < 2; it++) {
                int e = tid + it * 512;
                int n = e >> 3, q = e & 7;
                bRh[it] = *(const uint4*)(g_eBh + n * 256 + kn2 + q * 4);
                bRl[it] = *(const uint4*)(g_eBl + n * 256 + kn2 + q * 4);
            }
        }

#pragma unroll
        for (int ks2 = 0; ks2 < 32; ks2 += 8) {
            const int rb = wm * 16;
            uint32_t ah[4], al[4], bh[8][2], bl[8][2];
            ah[0] = Ah[(rb + g) * ST + ks2 + tg];
            ah[1] = Ah[(rb + g + 8) * ST + ks2 + tg];
            ah[2] = Ah[(rb + g) * ST + ks2 + tg + 4];
            ah[3] = Ah[(rb + g + 8) * ST + ks2 + tg + 4];
            al[0] = Al[(rb + g) * ST + ks2 + tg];
            al[1] = Al[(rb + g + 8) * ST + ks2 + tg];
            al[2] = Al[(rb + g) * ST + ks2 + tg + 4];
            al[3] = Al[(rb + g + 8) * ST + ks2 + tg + 4];
#pragma unroll
            for (int ni = 0; ni < 8; ni++) {
                int nb = wn * 64 + ni * 8;
                bh[ni][0] = Bh[(nb + g) * ST + ks2 + tg];
                bh[ni][1] = Bh[(nb + g) * ST + ks2 + tg + 4];
                bl[ni][0] = Bl[(nb + g) * ST + ks2 + tg];
                bl[ni][1] = Bl[(nb + g) * ST + ks2 + tg + 4];
            }
#pragma unroll
            for (int ni = 0; ni < 8; ni++) {
                mma_bf16(c[ni], ah[0], ah[1], ah[2], ah[3], bh[ni][0], bh[ni][1]);
                mma_bf16(c[ni], ah[0], ah[1], ah[2], ah[3], bl[ni][0], bl[ni][1]);
                mma_bf16(c[ni], al[0], al[1], al[2], al[3], bh[ni][0], bh[ni][1]);
            }
        }
        __syncthreads();
    }

#pragma unroll
    for (int half = 0; half < 2; half++) {
        int row = row0 + wm * 16 + g + half * 8;
        if (row >= M) continue;
#pragma unroll
        for (int ni = 0; ni < 8; ni++) {
            int col = wn * 64 + ni * 8 + tg * 2;
            float2 o;
            o.x = c[ni][half * 2 + 0] + bias[col];
            o.y = c[ni][half * 2 + 1] + bias[col + 1];
            *(float2*)(g_h + (size_t)row * HID + col) = o;
        }
    }
}

// ---------------- persistent fused MLP: 512 threads, 16 warps of 16x64 ------
#define ST2 68
__global__ void __launch_bounds__(512, 1)
mlp_fused_kernel(const uint32_t* __restrict__ W1h, const uint32_t* __restrict__ W1l,
                 const uint32_t* __restrict__ W2h, const uint32_t* __restrict__ W2l,
                 const float* __restrict__ b1, const float* __restrict__ b2, int M) {
    extern __shared__ uint32_t sh[];
    uint32_t* Ah  = sh;
    uint32_t* Al  = sh + 128 * ST2;
    uint32_t* Wh1 = sh + 2 * 128 * ST2;
    uint32_t* Wl1 = sh + 3 * 128 * ST2;
    uint32_t* Wh2 = sh + 4 * 128 * ST2;
    uint32_t* Wl2 = sh + 5 * 128 * ST2;

    const int tid = threadIdx.x, lane = tid & 31, wid = tid >> 5;
    const int g = lane >> 2, tg = lane & 3;
    const int wm = wid & 7, wn = wid >> 3;

#pragma unroll
    for (int it = 0; it < 4; it++) {
        int e = tid + it * 512;                // 2048 uint4
        int n = e >> 4, q = e & 15;
        int o = n * ST2 + q * 4;
        *(uint4*)(Wh1 + o) = *(const uint4*)(W1h + n * 64 + q * 4);
        *(uint4*)(Wl1 + o) = *(const uint4*)(W1l + n * 64 + q * 4);
        *(uint4*)(Wh2 + o) = *(const uint4*)(W2h + n * 64 + q * 4);
        *(uint4*)(Wl2 + o) = *(const uint4*)(W2l + n * 64 + q * 4);
    }

    for (int tile = blockIdx.x; tile < N_TILES; tile += gridDim.x) {
        const int row0 = tile * 128;
        __syncthreads();
#pragma unroll
        for (int it = 0; it < 8; it++) {
            int e = tid + it * 512;            // 4096 float4
            int m = e >> 5, j = e & 31;
            int r = row0 + m;
            float4 v = make_float4(0.f, 0.f, 0.f, 0.f);
            if (r < M) v = *(const float4*)(g_z + (size_t)r * HID + j * 4);
            uint32_t h0, l0, h1, l1;
            split2(v.x, v.y, h0, l0);
            split2(v.z, v.w, h1, l1);
            int o = m * ST2 + j * 2;
            Ah[o] = h0; Ah[o + 1] = h1;
            Al[o] = l0; Al[o + 1] = l1;
        }
        __syncthreads();

        float c[8][4];
#pragma unroll
        for (int ni = 0; ni < 8; ni++)
#pragma unroll
            for (int q = 0; q < 4; q++) c[ni][q] = 0.f;

        // GEMM1
#pragma unroll
        for (int ks2 = 0; ks2 < 64; ks2 += 8) {
            const int rb = wm * 16;
            uint32_t ah[4], al[4], bh[8][2], bl[8][2];
            ah[0] = Ah[(rb + g) * ST2 + ks2 + tg];
            ah[1] = Ah[(rb + g + 8) * ST2 + ks2 + tg];
            ah[2] = Ah[(rb + g) * ST2 + ks2 + tg + 4];
            ah[3] = Ah[(rb + g + 8) * ST2 + ks2 + tg + 4];
            al[0] = Al[(rb + g) * ST2 + ks2 + tg];
            al[1] = Al[(rb + g + 8) * ST2 + ks2 + tg];
            al[2] = Al[(rb + g) * ST2 + ks2 + tg + 4];
            al[3] = Al[(rb + g + 8) * ST2 + ks2 + tg + 4];
#pragma unroll
            for (int ni = 0; ni < 8; ni++) {
                int nb = wn * 64 + ni * 8;
                bh[ni][0] = Wh1[(nb + g) * ST2 + ks2 + tg];
                bh[ni][1] = Wh1[(nb + g) * ST2 + ks2 + tg + 4];
                bl[ni][0] = Wl1[(nb + g) * ST2 + ks2 + tg];
                bl[ni][1] = Wl1[(nb + g) * ST2 + ks2 + tg + 4];
            }
#pragma unroll
            for (int ni = 0; ni < 8; ni++) {
                mma_bf16(c[ni], ah[0], ah[1], ah[2], ah[3], bh[ni][0], bh[ni][1]);
                mma_bf16(c[ni], ah[0], ah[1], ah[2], ah[3], bl[ni][0], bl[ni][1]);
                mma_bf16(c[ni], al[0], al[1], al[2], al[3], bh[ni][0], bh[ni][1]);
            }
        }
        __syncthreads();

        // relu(c + b1) -> split -> Ah/Al
#pragma unroll
        for (int ni = 0; ni < 8; ni++) {
            int col = wn * 64 + ni * 8 + tg * 2;
            float bb0 = b1[col], bb1 = b1[col + 1];
            int k2 = wn * 32 + ni * 4 + tg;
            int r0 = wm * 16 + g;
            uint32_t hi, lo;
            split2(fmaxf(c[ni][0] + bb0, 0.f), fmaxf(c[ni][1] + bb1, 0.f), hi, lo);
            Ah[r0 * ST2 + k2] = hi; Al[r0 * ST2 + k2] = lo;
            split2(fmaxf(c[ni][2] + bb0, 0.f), fmaxf(c[ni][3] + bb1, 0.f), hi, lo);
            Ah[(r0 + 8) * ST2 + k2] = hi; Al[(r0 + 8) * ST2 + k2] = lo;
        }
        __syncthreads();

#pragma unroll
        for (int ni = 0; ni < 8; ni++)
#pragma unroll
            for (int q = 0; q < 4; q++) c[ni][q] = 0.f;

        // GEMM2
#pragma unroll
        for (int ks2 = 0; ks2 < 64; ks2 += 8) {
            const int rb = wm * 16;
            uint32_t ah[4], al[4], bh[8][2], bl[8][2];
            ah[0] = Ah[(rb + g) * ST2 + ks2 + tg];
            ah[1] = Ah[(rb + g + 8) * ST2 + ks2 + tg];
            ah[2] = Ah[(rb + g) * ST2 + ks2 + tg + 4];
            ah[3] = Ah[(rb + g + 8) * ST2 + ks2 + tg + 4];
            al[0] = Al[(rb + g) * ST2 + ks2 + tg];
            al[1] = Al[(rb + g + 8) * ST2 + ks2 + tg];
            al[2] = Al[(rb + g) * ST2 + ks2 + tg + 4];
            al[3] = Al[(rb + g + 8) * ST2 + ks2 + tg + 4];
#pragma unroll
            for (int ni = 0; ni < 8; ni++) {
                int nb = wn * 64 + ni * 8;
                bh[ni][0] = Wh2[(nb + g) * ST2 + ks2 + tg];
                bh[ni][1] = Wh2[(nb + g) * ST2 + ks2 + tg + 4];
                bl[ni][0] = Wl2[(nb + g) * ST2 + ks2 + tg];
                bl[ni][1] = Wl2[(nb + g) * ST2 + ks2 + tg + 4];
            }
#pragma unroll
            for (int ni = 0; ni < 8; ni++) {
                mma_bf16(c[ni], ah[0], ah[1], ah[2], ah[3], bh[ni][0], bh[ni][1]);
                mma_bf16(c[ni], ah[0], ah[1], ah[2], ah[3], bl[ni][0], bl[ni][1]);
                mma_bf16(c[ni], al[0], al[1], al[2], al[3], bh[ni][0], bh[ni][1]);
            }
        }

#pragma unroll
        for (int half = 0; half < 2; half++) {
            int row = row0 + wm * 16 + g + half * 8;
            if (row >= M) continue;
#pragma unroll
            for (int ni = 0; ni < 8; ni++) {
                int col = wn * 64 + ni * 8 + tg * 2;
                float2 o;
                o.x = fmaxf(c[ni][half * 2 + 0] + b2[col], 0.f);
                o.y = fmaxf(c[ni][half * 2 + 1] + b2[col + 1], 0.f);
                *(float2*)(g_h + (size_t)row * HID + col) = o;
            }
        }
    }
}

// ---------------- aggregation ------------------------------------------------
__global__ void agg_kernel() {
    int node = (blockIdx.x * blockDim.x + threadIdx.x) >> 5;
    int lane = threadIdx.x & 31;
    if (node >= N_NODES) return;
    int s = g_off[node];
    int d = g_deg[node];
    float4 acc = *(const float4*)(g_h + (size_t)node * HID + lane * 4);
    int i = 0;
    for (; i + 2 <= d; i += 2) {
        uint2 e0 = g_edge[s + i];
        uint2 e1 = g_edge[s + i + 1];
        float w0 = __uint_as_float(e0.y);
        float w1 = __uint_as_float(e1.y);
        float4 h0 = *(const float4*)(g_h + (size_t)e0.x * HID + lane * 4);
        float4 h1 = *(const float4*)(g_h + (size_t)e1.x * HID + lane * 4);
        acc.x += w0 * h0.x + w1 * h1.x;
        acc.y += w0 * h0.y + w1 * h1.y;
        acc.z += w0 * h0.z + w1 * h1.z;
        acc.w += w0 * h0.w + w1 * h1.w;
    }
    if (i < d) {
        uint2 e0 = g_edge[s + i];
        float w0 = __uint_as_float(e0.y);
        float4 h0 = *(const float4*)(g_h + (size_t)e0.x * HID + lane * 4);
        acc.x += w0 * h0.x; acc.y += w0 * h0.y;
        acc.z += w0 * h0.z; acc.w += w0 * h0.w;
    }
    *(float4*)(g_z + (size_t)node * HID + lane * 4) = acc;
}

// ---------------- readout ----------------------------------------------------
__global__ void readout_kernel(const float* __restrict__ Wr,
                               const float* __restrict__ br,
                               float* __restrict__ out, int M) {
    extern __shared__ float sm[];
    float* hs = sm;
    float* wt = sm + 128 * 132;
    const int row0 = blockIdx.x * 128;
    const int tr = threadIdx.x >> 3;
    const int cg = threadIdx.x & 7;

    for (int e = threadIdx.x; e < 128 * 128; e += 256) {
        int m = e >> 7, k = e & 127;
        int r = row0 + m;
        hs[m * 132 + k] = (r < M) ? g_h[(size_t)r * HID + k] : 0.f;
    }
    for (int e = threadIdx.x; e < 128 * OUT_DIM; e += 256) {
        int k = e / OUT_DIM, c = e % OUT_DIM;
        wt[c * 132 + k] = Wr[e];
    }
    __syncthreads();

    float acc[4][5];
#pragma unroll
    for (int r = 0; r < 4; r++)
#pragma unroll
        for (int c = 0; c < 5; c++) acc[r][c] = 0.f;

    for (int k = 0; k < 128; k += 4) {
        float4 hv[4];
#pragma unroll
        for (int r = 0; r < 4; r++)
            hv[r] = *(const float4*)(hs + (tr * 4 + r) * 132 + k);
#pragma unroll
        for (int c = 0; c < 5; c++) {
            float4 wv = *(const float4*)(wt + (cg * 5 + c) * 132 + k);
#pragma unroll
            for (int r = 0; r < 4; r++)
                acc[r][c] += hv[r].x * wv.x + hv[r].y * wv.y
                           + hv[r].z * wv.z + hv[r].w * wv.w;
        }
    }
#pragma unroll
    for (int r = 0; r < 4; r++) {
        int row = row0 + tr * 4 + r;
        if (row < M) {
#pragma unroll
            for (int c = 0; c < 5; c++) {
                int col = cg * 5 + c;
                out[(size_t)row * OUT_DIM + col] = acc[r][c] + br[col];
            }
        }
    }
}

// ---------------- launch ----------------------------------------------------
extern "C" void kernel_launch(void* const* d_in, const int* in_sizes, int n_in,
                              void* d_out, int out_size) {
    const float* features = (const float*)d_in[0];
    const int*   src      = (const int*)  d_in[1];
    const int*   dst      = (const int*)  d_in[2];
    const float* edge_w   = (const float*)d_in[3];
    const float* emb_W    = (const float*)d_in[4];
    const float* emb_b    = (const float*)d_in[5];
    const float* W1       = (const float*)d_in[6];
    const float* b1       = (const float*)d_in[7];
    const float* W2       = (const float*)d_in[8];
    const float* b2       = (const float*)d_in[9];
    const float* ro_W     = (const float*)d_in[10];
    const float* ro_b     = (const float*)d_in[11];
    float* out = (float*)d_out;

    const int emb_smem = 4 * 128 * ST  * (int)sizeof(uint32_t);
    const int mlp_smem = 6 * 128 * ST2 * (int)sizeof(uint32_t);
    const int ro_smem  = (128 * 132 + OUT_DIM * 132) * (int)sizeof(float);
    cudaFuncSetAttribute(emb_gemm_kernel,  cudaFuncAttributeMaxDynamicSharedMemorySize, emb_smem);
    cudaFuncSetAttribute(mlp_fused_kernel, cudaFuncAttributeMaxDynamicSharedMemorySize, mlp_smem);
    cudaFuncSetAttribute(readout_kernel,   cudaFuncAttributeMaxDynamicSharedMemorySize, ro_smem);

    uint32_t *d_W1h, *d_W1l, *d_W2h, *d_W2l;
    cudaGetSymbolAddress((void**)&d_W1h, g_W1h);
    cudaGetSymbolAddress((void**)&d_W1l, g_W1l);
    cudaGetSymbolAddress((void**)&d_W2h, g_W2h);
    cudaGetSymbolAddress((void**)&d_W2l, g_W2l);

    cudaStream_t side = cudaStreamPerThread;
    cudaEvent_t evA, evB;
    cudaEventCreateWithFlags(&evA, cudaEventDisableTiming);
    cudaEventCreateWithFlags(&evB, cudaEventDisableTiming);

    cudaEventRecord(evA, 0);
    cudaStreamWaitEvent(side, evA, 0);

    prep_emb_kernel<<<HID * 256 / 256, 256>>>(emb_W);                         // main #0
    prep_w_kernel<<<(N_LAYERS * HID * 64 + 255) / 256, 256>>>(W1, W2);        // main #1
    zero_deg_kernel<<<(N_NODES + 255) / 256, 256, 0, side>>>();               // side #2
    emb_gemm_kernel<<<N_TILES, 512, emb_smem>>>(features, emb_b, N_NODES);    // main #3 <- profiled
    hist_kernel<<<(N_EDGES + 255) / 256, 256, 0, side>>>(dst);
    scan1_kernel<<<NB_SCAN, 1024, 0, side>>>();
    scan23_kernel<<<NB_SCAN, 1024, 0, side>>>();
    scatter_kernel<<<(N_EDGES + 255) / 256, 256, 0, side>>>(src, dst, edge_w);

    cudaEventRecord(evB, side);
    cudaStreamWaitEvent(0, evB, 0);

    const int agg_blocks = (N_NODES * 32 + 255) / 256;
    for (int l = 0; l < N_LAYERS; l++) {
        agg_kernel<<<agg_blocks, 256>>>();
        mlp_fused_kernel<<<148, 512, mlp_smem>>>(
            d_W1h + (size_t)l * HID * 64, d_W1l + (size_t)l * HID * 64,
            d_W2h + (size_t)l * HID * 64, d_W2l + (size_t)l * HID * 64,
            b1 + (size_t)l * HID, b2 + (size_t)l * HID, N_NODES);
    }
    readout_kernel<<<N_TILES, 256, ro_smem>>>(ro_W, ro_b, out, N_NODES);
}

// round 8
// speedup vs baseline: 1.0437x; 1.0437x over previous
#include <cuda_runtime.h>
#include <cuda_bf16.h>
#include <cstdint>

#define N_NODES 50000
#define N_EDGES 625000
#define IN_DIM  512
#define HID     128
#define OUT_DIM 40
#define N_LAYERS 3
#define NB_SCAN ((N_NODES + 1023) / 1024)
#define N_TILES ((N_NODES + 127) / 128)

// ---------------- scratch ---------------------------------------------------
__device__ float g_h[N_NODES * HID];
__device__ float g_z[N_NODES * HID];
__device__ int   g_deg[N_NODES];
__device__ int   g_off[N_NODES];
__device__ int   g_cur[N_NODES];
__device__ uint2 g_edge[N_EDGES];          // {src, w_bits}
__device__ int   g_bsum[64];
__device__ uint32_t g_eBh[HID * (IN_DIM / 2)];
__device__ uint32_t g_eBl[HID * (IN_DIM / 2)];
__device__ uint32_t g_W1h[N_LAYERS * HID * (HID / 2)];
__device__ uint32_t g_W1l[N_LAYERS * HID * (HID / 2)];
__device__ uint32_t g_W2h[N_LAYERS * HID * (HID / 2)];
__device__ uint32_t g_W2l[N_LAYERS * HID * (HID / 2)];

// ---------------- helpers ----------------------------------------------------
__device__ __forceinline__ uint32_t smem_u32(const void* p) {
    uint32_t a;
    asm("{ .reg .u64 t; cvta.to.shared.u64 t, %1; cvt.u32.u64 %0, t; }" : "=r"(a) : "l"(p));
    return a;
}
__device__ __forceinline__ void split2(float v0, float v1, uint32_t& hi, uint32_t& lo) {
    uint16_t h0, h1, l0, l1;
    asm("cvt.rn.bf16.f32 %0, %1;" : "=h"(h0) : "f"(v0));
    asm("cvt.rn.bf16.f32 %0, %1;" : "=h"(h1) : "f"(v1));
    float r0 = v0 - __uint_as_float((uint32_t)h0 << 16);
    float r1 = v1 - __uint_as_float((uint32_t)h1 << 16);
    asm("cvt.rn.bf16.f32 %0, %1;" : "=h"(l0) : "f"(r0));
    asm("cvt.rn.bf16.f32 %0, %1;" : "=h"(l1) : "f"(r1));
    hi = ((uint32_t)h1 << 16) | h0;
    lo = ((uint32_t)l1 << 16) | l0;
}
__device__ __forceinline__ void mma_bf16(float* c, uint32_t a0, uint32_t a1,
                                         uint32_t a2, uint32_t a3,
                                         uint32_t b0, uint32_t b1) {
    asm volatile("mma.sync.aligned.m16n8k16.row.col.f32.bf16.bf16.f32 "
                 "{%0,%1,%2,%3}, {%4,%5,%6,%7}, {%8,%9}, {%0,%1,%2,%3};"
                 : "+f"(c[0]), "+f"(c[1]), "+f"(c[2]), "+f"(c[3])
                 : "r"(a0), "r"(a1), "r"(a2), "r"(a3), "r"(b0), "r"(b1));
}
__device__ __forceinline__ void ldsm_x4(uint32_t& r0, uint32_t& r1, uint32_t& r2,
                                        uint32_t& r3, uint32_t addr) {
    asm volatile("ldmatrix.sync.aligned.m8n8.x4.shared.b16 {%0,%1,%2,%3}, [%4];"
                 : "=r"(r0), "=r"(r1), "=r"(r2), "=r"(r3) : "r"(addr));
}

// ---------------- CSR build -------------------------------------------------
__global__ void zero_deg_kernel() {
    int i = blockIdx.x * blockDim.x + threadIdx.x;
    if (i < N_NODES) g_deg[i] = 0;
}
__global__ void hist_kernel(const int* __restrict__ dst) {
    int e = blockIdx.x * blockDim.x + threadIdx.x;
    if (e < N_EDGES) atomicAdd(&g_deg[dst[e]], 1);
}
__global__ void scan1_kernel() {
    __shared__ int s[1024];
    int t = threadIdx.x;
    int i = blockIdx.x * 1024 + t;
    int v = (i < N_NODES) ? g_deg[i] : 0;
    s[t] = v;
    __syncthreads();
    for (int d = 1; d < 1024; d <<= 1) {
        int tmp = (t >= d) ? s[t - d] : 0;
        __syncthreads();
        s[t] += tmp;
        __syncthreads();
    }
    if (i < N_NODES) g_off[i] = s[t] - v;
    if (t == 1023) g_bsum[blockIdx.x] = s[1023];
}
__global__ void scan23_kernel() {
    __shared__ int red[64];
    __shared__ int base_s;
    int t = threadIdx.x;
    if (t < 64) red[t] = (t < NB_SCAN && t < (int)blockIdx.x) ? g_bsum[t] : 0;
    __syncthreads();
    if (t < 32) {
        int s = red[t] + red[t + 32];
        for (int d = 16; d > 0; d >>= 1) s += __shfl_down_sync(0xffffffffu, s, d);
        if (t == 0) base_s = s;
    }
    __syncthreads();
    int i = blockIdx.x * 1024 + t;
    if (i < N_NODES) {
        int o = g_off[i] + base_s;
        g_off[i] = o;
        g_cur[i] = o;
    }
}
__global__ void scatter_kernel(const int* __restrict__ src,
                               const int* __restrict__ dst,
                               const float* __restrict__ ew) {
    int e = blockIdx.x * blockDim.x + threadIdx.x;
    if (e < N_EDGES) {
        int d = dst[e];
        int pos = atomicAdd(&g_cur[d], 1);
        g_edge[pos] = make_uint2((uint32_t)src[e], __float_as_uint(ew[e]));
    }
}

// ---------------- weight prep ------------------------------------------------
__global__ void prep_emb_kernel(const float* __restrict__ W) {
    int idx = blockIdx.x * blockDim.x + threadIdx.x;
    int n = idx >> 8, k2 = idx & 255;
    uint32_t hi, lo;
    split2(W[(size_t)(2 * k2) * HID + n], W[(size_t)(2 * k2 + 1) * HID + n], hi, lo);
    g_eBh[n * 256 + k2] = hi;
    g_eBl[n * 256 + k2] = lo;
}
__global__ void prep_w_kernel(const float* __restrict__ W1, const float* __restrict__ W2) {
    int idx = blockIdx.x * blockDim.x + threadIdx.x;
    if (idx >= N_LAYERS * HID * 64) return;
    int l = idx / (HID * 64);
    int rem = idx - l * HID * 64;
    int n = rem >> 6, k2 = rem & 63;
    const float* w1 = W1 + (size_t)l * HID * HID;
    const float* w2 = W2 + (size_t)l * HID * HID;
    uint32_t hi, lo;
    split2(w1[(2 * k2) * HID + n], w1[(2 * k2 + 1) * HID + n], hi, lo);
    g_W1h[idx] = hi; g_W1l[idx] = lo;
    split2(w2[(2 * k2) * HID + n], w2[(2 * k2 + 1) * HID + n], hi, lo);
    g_W2h[idx] = hi; g_W2l[idx] = lo;
}

// ---------------- emb GEMM: 512 threads, ldmatrix fragments -----------------
#define ST 36
__global__ void __launch_bounds__(512, 1)
emb_gemm_kernel(const float* __restrict__ A, const float* __restrict__ bias, int M) {
    extern __shared__ uint32_t sh[];
    uint32_t* Ah = sh;
    uint32_t* Al = sh + 128 * ST;
    uint32_t* Bh = sh + 2 * 128 * ST;
    uint32_t* Bl = sh + 3 * 128 * ST;

    const int tid = threadIdx.x, lane = tid & 31, wid = tid >> 5;
    const int g = lane >> 2, tg = lane & 3;
    const int wm = wid & 7, wn = wid >> 3;     // 8 x 2 warps, 16x64 tiles
    const int row0 = blockIdx.x * 128;

    // ldmatrix lane addressing
    const int lr = lane & 7, lo8 = (lane >> 3) & 1, hi16 = (lane >> 4) & 1;
    const uint32_t AhB = smem_u32(Ah), AlB = smem_u32(Al);
    const uint32_t BhB = smem_u32(Bh), BlB = smem_u32(Bl);
    const int aRowOff = (wm * 16 + lr + 8 * lo8) * ST + 4 * hi16;         // words
    const int bRowOff = (wn * 64 + lr + 8 * hi16) * ST + 4 * lo8;         // words

    float4 aR[4];
    uint4  bRh[2], bRl[2];

#pragma unroll
    for (int it = 0; it < 4; it++) {
        int e = tid + it * 512;
        int m = e >> 4, j = e & 15;
        int r = row0 + m;
        aR[it] = make_float4(0.f, 0.f, 0.f, 0.f);
        if (r < M) aR[it] = *(const float4*)(A + (size_t)r * IN_DIM + j * 4);
    }
#pragma unroll
    for (int it = 0; it < 2; it++) {
        int e = tid + it * 512;
        int n = e >> 3, q = e & 7;
        bRh[it] = *(const uint4*)(g_eBh + n * 256 + q * 4);
        bRl[it] = *(const uint4*)(g_eBl + n * 256 + q * 4);
    }

    float c[8][4];
#pragma unroll
    for (int ni = 0; ni < 8; ni++)
#pragma unroll
        for (int q = 0; q < 4; q++) c[ni][q] = 0.f;

    for (int kc = 0; kc < IN_DIM; kc += 64) {
#pragma unroll
        for (int it = 0; it < 4; it++) {
            int e = tid + it * 512;
            int m = e >> 4, j = e & 15;
            uint32_t h0, l0, h1, l1;
            split2(aR[it].x, aR[it].y, h0, l0);
            split2(aR[it].z, aR[it].w, h1, l1);
            int o = m * ST + j * 2;
            Ah[o] = h0; Ah[o + 1] = h1;
            Al[o] = l0; Al[o + 1] = l1;
        }
#pragma unroll
        for (int it = 0; it < 2; it++) {
            int e = tid + it * 512;
            int n = e >> 3, q = e & 7;
            int o = n * ST + q * 4;
            *(uint4*)(Bh + o) = bRh[it];
            *(uint4*)(Bl + o) = bRl[it];
        }
        __syncthreads();

        if (kc + 64 < IN_DIM) {
            int kn = kc + 64, kn2 = kn >> 1;
#pragma unroll
            for (int it = 0; it < 4; it++) {
                int e = tid + it * 512;
                int m = e >> 4, j = e & 15;
                int r = row0 + m;
                aR[it] = make_float4(0.f, 0.f, 0.f, 0.f);
                if (r < M) aR[it] = *(const float4*)(A + (size_t)r * IN_DIM + kn + j * 4);
            }
#pragma unroll
            for (int it = 0; it < 2; it++) {
                int e = tid + it * 512;
                int n = e >> 3, q = e & 7;
                bRh[it] = *(const uint4*)(g_eBh + n * 256 + kn2 + q * 4);
                bRl[it] = *(const uint4*)(g_eBl + n * 256 + kn2 + q * 4);
            }
        }

#pragma unroll
        for (int ks2 = 0; ks2 < 32; ks2 += 8) {
            uint32_t a0, a1, a2, a3, l0, l1, l2, l3;
            ldsm_x4(a0, a1, a2, a3, AhB + (uint32_t)(aRowOff + ks2) * 4u);
            ldsm_x4(l0, l1, l2, l3, AlB + (uint32_t)(aRowOff + ks2) * 4u);
            uint32_t bh[8][2], bl[8][2];
#pragma unroll
            for (int p = 0; p < 4; p++) {
                uint32_t r0, r1, r2, r3;
                ldsm_x4(r0, r1, r2, r3, BhB + (uint32_t)(bRowOff + p * 16 * ST + ks2) * 4u);
                bh[2 * p][0] = r0; bh[2 * p][1] = r1;
                bh[2 * p + 1][0] = r2; bh[2 * p + 1][1] = r3;
                ldsm_x4(r0, r1, r2, r3, BlB + (uint32_t)(bRowOff + p * 16 * ST + ks2) * 4u);
                bl[2 * p][0] = r0; bl[2 * p][1] = r1;
                bl[2 * p + 1][0] = r2; bl[2 * p + 1][1] = r3;
            }
#pragma unroll
            for (int ni = 0; ni < 8; ni++) {
                mma_bf16(c[ni], a0, a1, a2, a3, bh[ni][0], bh[ni][1]);
                mma_bf16(c[ni], a0, a1, a2, a3, bl[ni][0], bl[ni][1]);
                mma_bf16(c[ni], l0, l1, l2, l3, bh[ni][0], bh[ni][1]);
            }
        }
        __syncthreads();
    }

#pragma unroll
    for (int half = 0; half < 2; half++) {
        int row = row0 + wm * 16 + g + half * 8;
        if (row >= M) continue;
#pragma unroll
        for (int ni = 0; ni < 8; ni++) {
            int col = wn * 64 + ni * 8 + tg * 2;
            float2 o;
            o.x = c[ni][half * 2 + 0] + bias[col];
            o.y = c[ni][half * 2 + 1] + bias[col + 1];
            *(float2*)(g_h + (size_t)row * HID + col) = o;
        }
    }
}

// ---------------- persistent fused MLP: ldmatrix fragments ------------------
#define ST2 68
__global__ void __launch_bounds__(512, 1)
mlp_fused_kernel(const uint32_t* __restrict__ W1h, const uint32_t* __restrict__ W1l,
                 const uint32_t* __restrict__ W2h, const uint32_t* __restrict__ W2l,
                 const float* __restrict__ b1, const float* __restrict__ b2, int M) {
    extern __shared__ uint32_t sh[];
    uint32_t* Ah  = sh;
    uint32_t* Al  = sh + 128 * ST2;
    uint32_t* Wh1 = sh + 2 * 128 * ST2;
    uint32_t* Wl1 = sh + 3 * 128 * ST2;
    uint32_t* Wh2 = sh + 4 * 128 * ST2;
    uint32_t* Wl2 = sh + 5 * 128 * ST2;

    const int tid = threadIdx.x, lane = tid & 31, wid = tid >> 5;
    const int g = lane >> 2, tg = lane & 3;
    const int wm = wid & 7, wn = wid >> 3;

    const int lr = lane & 7, lo8 = (lane >> 3) & 1, hi16 = (lane >> 4) & 1;
    const uint32_t AhB  = smem_u32(Ah),  AlB  = smem_u32(Al);
    const uint32_t Wh1B = smem_u32(Wh1), Wl1B = smem_u32(Wl1);
    const uint32_t Wh2B = smem_u32(Wh2), Wl2B = smem_u32(Wl2);
    const int aRowOff = (wm * 16 + lr + 8 * lo8) * ST2 + 4 * hi16;
    const int bRowOff = (wn * 64 + lr + 8 * hi16) * ST2 + 4 * lo8;

#pragma unroll
    for (int it = 0; it < 4; it++) {
        int e = tid + it * 512;
        int n = e >> 4, q = e & 15;
        int o = n * ST2 + q * 4;
        *(uint4*)(Wh1 + o) = *(const uint4*)(W1h + n * 64 + q * 4);
        *(uint4*)(Wl1 + o) = *(const uint4*)(W1l + n * 64 + q * 4);
        *(uint4*)(Wh2 + o) = *(const uint4*)(W2h + n * 64 + q * 4);
        *(uint4*)(Wl2 + o) = *(const uint4*)(W2l + n * 64 + q * 4);
    }

    for (int tile = blockIdx.x; tile < N_TILES; tile += gridDim.x) {
        const int row0 = tile * 128;
        __syncthreads();
#pragma unroll
        for (int it = 0; it < 8; it++) {
            int e = tid + it * 512;
            int m = e >> 5, j = e & 31;
            int r = row0 + m;
            float4 v = make_float4(0.f, 0.f, 0.f, 0.f);
            if (r < M) v = *(const float4*)(g_z + (size_t)r * HID + j * 4);
            uint32_t h0, l0, h1, l1;
            split2(v.x, v.y, h0, l0);
            split2(v.z, v.w, h1, l1);
            int o = m * ST2 + j * 2;
            Ah[o] = h0; Ah[o + 1] = h1;
            Al[o] = l0; Al[o + 1] = l1;
        }
        __syncthreads();

        float c[8][4];
#pragma unroll
        for (int ni = 0; ni < 8; ni++)
#pragma unroll
            for (int q = 0; q < 4; q++) c[ni][q] = 0.f;

        // GEMM1
#pragma unroll
        for (int ks2 = 0; ks2 < 64; ks2 += 8) {
            uint32_t a0, a1, a2, a3, l0, l1, l2, l3;
            ldsm_x4(a0, a1, a2, a3, AhB + (uint32_t)(aRowOff + ks2) * 4u);
            ldsm_x4(l0, l1, l2, l3, AlB + (uint32_t)(aRowOff + ks2) * 4u);
            uint32_t bh[8][2], bl[8][2];
#pragma unroll
            for (int p = 0; p < 4; p++) {
                uint32_t r0, r1, r2, r3;
                ldsm_x4(r0, r1, r2, r3, Wh1B + (uint32_t)(bRowOff + p * 16 * ST2 + ks2) * 4u);
                bh[2 * p][0] = r0; bh[2 * p][1] = r1;
                bh[2 * p + 1][0] = r2; bh[2 * p + 1][1] = r3;
                ldsm_x4(r0, r1, r2, r3, Wl1B + (uint32_t)(bRowOff + p * 16 * ST2 + ks2) * 4u);
                bl[2 * p][0] = r0; bl[2 * p][1] = r1;
                bl[2 * p + 1][0] = r2; bl[2 * p + 1][1] = r3;
            }
#pragma unroll
            for (int ni = 0; ni < 8; ni++) {
                mma_bf16(c[ni], a0, a1, a2, a3, bh[ni][0], bh[ni][1]);
                mma_bf16(c[ni], a0, a1, a2, a3, bl[ni][0], bl[ni][1]);
                mma_bf16(c[ni], l0, l1, l2, l3, bh[ni][0], bh[ni][1]);
            }
        }
        __syncthreads();

        // relu(c + b1) -> split -> Ah/Al
#pragma unroll
        for (int ni = 0; ni < 8; ni++) {
            int col = wn * 64 + ni * 8 + tg * 2;
            float bb0 = b1[col], bb1 = b1[col + 1];
            int k2 = wn * 32 + ni * 4 + tg;
            int r0 = wm * 16 + g;
            uint32_t hi, lo;
            split2(fmaxf(c[ni][0] + bb0, 0.f), fmaxf(c[ni][1] + bb1, 0.f), hi, lo);
            Ah[r0 * ST2 + k2] = hi; Al[r0 * ST2 + k2] = lo;
            split2(fmaxf(c[ni][2] + bb0, 0.f), fmaxf(c[ni][3] + bb1, 0.f), hi, lo);
            Ah[(r0 + 8) * ST2 + k2] = hi; Al[(r0 + 8) * ST2 + k2] = lo;
        }
        __syncthreads();

#pragma unroll
        for (int ni = 0; ni < 8; ni++)
#pragma unroll
            for (int q = 0; q < 4; q++) c[ni][q] = 0.f;

        // GEMM2
#pragma unroll
        for (int ks2 = 0; ks2 < 64; ks2 += 8) {
            uint32_t a0, a1, a2, a3, l0, l1, l2, l3;
            ldsm_x4(a0, a1, a2, a3, AhB + (uint32_t)(aRowOff + ks2) * 4u);
            ldsm_x4(l0, l1, l2, l3, AlB + (uint32_t)(aRowOff + ks2) * 4u);
            uint32_t bh[8][2], bl[8][2];
#pragma unroll
            for (int p = 0; p < 4; p++) {
                uint32_t r0, r1, r2, r3;
                ldsm_x4(r0, r1, r2, r3, Wh2B + (uint32_t)(bRowOff + p * 16 * ST2 + ks2) * 4u);
                bh[2 * p][0] = r0; bh[2 * p][1] = r1;
                bh[2 * p + 1][0] = r2; bh[2 * p + 1][1] = r3;
                ldsm_x4(r0, r1, r2, r3, Wl2B + (uint32_t)(bRowOff + p * 16 * ST2 + ks2) * 4u);
                bl[2 * p][0] = r0; bl[2 * p][1] = r1;
                bl[2 * p + 1][0] = r2; bl[2 * p + 1][1] = r3;
            }
#pragma unroll
            for (int ni = 0; ni < 8; ni++) {
                mma_bf16(c[ni], a0, a1, a2, a3, bh[ni][0], bh[ni][1]);
                mma_bf16(c[ni], a0, a1, a2, a3, bl[ni][0], bl[ni][1]);
                mma_bf16(c[ni], l0, l1, l2, l3, bh[ni][0], bh[ni][1]);
            }
        }

#pragma unroll
        for (int half = 0; half < 2; half++) {
            int row = row0 + wm * 16 + g + half * 8;
            if (row >= M) continue;
#pragma unroll
            for (int ni = 0; ni < 8; ni++) {
                int col = wn * 64 + ni * 8 + tg * 2;
                float2 o;
                o.x = fmaxf(c[ni][half * 2 + 0] + b2[col], 0.f);
                o.y = fmaxf(c[ni][half * 2 + 1] + b2[col + 1], 0.f);
                *(float2*)(g_h + (size_t)row * HID + col) = o;
            }
        }
    }
}

// ---------------- aggregation ------------------------------------------------
__global__ void agg_kernel() {
    int node = (blockIdx.x * blockDim.x + threadIdx.x) >> 5;
    int lane = threadIdx.x & 31;
    if (node >= N_NODES) return;
    int s = g_off[node];
    int d = g_deg[node];
    float4 acc = *(const float4*)(g_h + (size_t)node * HID + lane * 4);
    int i = 0;
    for (; i + 2 <= d; i += 2) {
        uint2 e0 = g_edge[s + i];
        uint2 e1 = g_edge[s + i + 1];
        float w0 = __uint_as_float(e0.y);
        float w1 = __uint_as_float(e1.y);
        float4 h0 = *(const float4*)(g_h + (size_t)e0.x * HID + lane * 4);
        float4 h1 = *(const float4*)(g_h + (size_t)e1.x * HID + lane * 4);
        acc.x += w0 * h0.x + w1 * h1.x;
        acc.y += w0 * h0.y + w1 * h1.y;
        acc.z += w0 * h0.z + w1 * h1.z;
        acc.w += w0 * h0.w + w1 * h1.w;
    }
    if (i < d) {
        uint2 e0 = g_edge[s + i];
        float w0 = __uint_as_float(e0.y);
        float4 h0 = *(const float4*)(g_h + (size_t)e0.x * HID + lane * 4);
        acc.x += w0 * h0.x; acc.y += w0 * h0.y;
        acc.z += w0 * h0.z; acc.w += w0 * h0.w;
    }
    *(float4*)(g_z + (size_t)node * HID + lane * 4) = acc;
}

// ---------------- readout ----------------------------------------------------
__global__ void readout_kernel(const float* __restrict__ Wr,
                               const float* __restrict__ br,
                               float* __restrict__ out, int M) {
    extern __shared__ float sm[];
    float* hs = sm;
    float* wt = sm + 128 * 132;
    const int row0 = blockIdx.x * 128;
    const int tr = threadIdx.x >> 3;
    const int cg = threadIdx.x & 7;

    for (int e = threadIdx.x; e < 128 * 128; e += 256) {
        int m = e >> 7, k = e & 127;
        int r = row0 + m;
        hs[m * 132 + k] = (r < M) ? g_h[(size_t)r * HID + k] : 0.f;
    }
    for (int e = threadIdx.x; e < 128 * OUT_DIM; e += 256) {
        int k = e / OUT_DIM, c = e % OUT_DIM;
        wt[c * 132 + k] = Wr[e];
    }
    __syncthreads();

    float acc[4][5];
#pragma unroll
    for (int r = 0; r < 4; r++)
#pragma unroll
        for (int c = 0; c < 5; c++) acc[r][c] = 0.f;

    for (int k = 0; k < 128; k += 4) {
        float4 hv[4];
#pragma unroll
        for (int r = 0; r < 4; r++)
            hv[r] = *(const float4*)(hs + (tr * 4 + r) * 132 + k);
#pragma unroll
        for (int c = 0; c < 5; c++) {
            float4 wv = *(const float4*)(wt + (cg * 5 + c) * 132 + k);
#pragma unroll
            for (int r = 0; r < 4; r++)
                acc[r][c] += hv[r].x * wv.x + hv[r].y * wv.y
                           + hv[r].z * wv.z + hv[r].w * wv.w;
        }
    }
#pragma unroll
    for (int r = 0; r < 4; r++) {
        int row = row0 + tr * 4 + r;
        if (row < M) {
#pragma unroll
            for (int c = 0; c < 5; c++) {
                int col = cg * 5 + c;
                out[(size_t)row * OUT_DIM + col] = acc[r][c] + br[col];
            }
        }
    }
}

// ---------------- launch ----------------------------------------------------
extern "C" void kernel_launch(void* const* d_in, const int* in_sizes, int n_in,
                              void* d_out, int out_size) {
    const float* features = (const float*)d_in[0];
    const int*   src      = (const int*)  d_in[1];
    const int*   dst      = (const int*)  d_in[2];
    const float* edge_w   = (const float*)d_in[3];
    const float* emb_W    = (const float*)d_in[4];
    const float* emb_b    = (const float*)d_in[5];
    const float* W1       = (const float*)d_in[6];
    const float* b1       = (const float*)d_in[7];
    const float* W2       = (const float*)d_in[8];
    const float* b2       = (const float*)d_in[9];
    const float* ro_W     = (const float*)d_in[10];
    const float* ro_b     = (const float*)d_in[11];
    float* out = (float*)d_out;

    const int emb_smem = 4 * 128 * ST  * (int)sizeof(uint32_t);
    const int mlp_smem = 6 * 128 * ST2 * (int)sizeof(uint32_t);
    const int ro_smem  = (128 * 132 + OUT_DIM * 132) * (int)sizeof(float);
    cudaFuncSetAttribute(emb_gemm_kernel,  cudaFuncAttributeMaxDynamicSharedMemorySize, emb_smem);
    cudaFuncSetAttribute(mlp_fused_kernel, cudaFuncAttributeMaxDynamicSharedMemorySize, mlp_smem);
    cudaFuncSetAttribute(readout_kernel,   cudaFuncAttributeMaxDynamicSharedMemorySize, ro_smem);

    uint32_t *d_W1h, *d_W1l, *d_W2h, *d_W2l;
    cudaGetSymbolAddress((void**)&d_W1h, g_W1h);
    cudaGetSymbolAddress((void**)&d_W1l, g_W1l);
    cudaGetSymbolAddress((void**)&d_W2h, g_W2h);
    cudaGetSymbolAddress((void**)&d_W2l, g_W2l);

    cudaStream_t side = cudaStreamPerThread;
    cudaEvent_t evA, evB;
    cudaEventCreateWithFlags(&evA, cudaEventDisableTiming);
    cudaEventCreateWithFlags(&evB, cudaEventDisableTiming);

    cudaEventRecord(evA, 0);
    cudaStreamWaitEvent(side, evA, 0);

    prep_emb_kernel<<<HID * 256 / 256, 256>>>(emb_W);                         // main #0
    prep_w_kernel<<<(N_LAYERS * HID * 64 + 255) / 256, 256>>>(W1, W2);        // main #1
    zero_deg_kernel<<<(N_NODES + 255) / 256, 256, 0, side>>>();               // side #2
    emb_gemm_kernel<<<N_TILES, 512, emb_smem>>>(features, emb_b, N_NODES);    // main #3 <- profiled
    hist_kernel<<<(N_EDGES + 255) / 256, 256, 0, side>>>(dst);
    scan1_kernel<<<NB_SCAN, 1024, 0, side>>>();
    scan23_kernel<<<NB_SCAN, 1024, 0, side>>>();
    scatter_kernel<<<(N_EDGES + 255) / 256, 256, 0, side>>>(src, dst, edge_w);

    cudaEventRecord(evB, side);
    cudaStreamWaitEvent(0, evB, 0);

    const int agg_blocks = (N_NODES * 32 + 255) / 256;
    for (int l = 0; l < N_LAYERS; l++) {
        agg_kernel<<<agg_blocks, 256>>>();
        mlp_fused_kernel<<<148, 512, mlp_smem>>>(
            d_W1h + (size_t)l * HID * 64, d_W1l + (size_t)l * HID * 64,
            d_W2h + (size_t)l * HID * 64, d_W2l + (size_t)l * HID * 64,
            b1 + (size_t)l * HID, b2 + (size_t)l * HID, N_NODES);
    }
    readout_kernel<<<N_TILES, 256, ro_smem>>>(ro_W, ro_b, out, N_NODES);
}

// round 9
// speedup vs baseline: 1.0529x; 1.0089x over previous
#include <cuda_runtime.h>
#include <cuda_bf16.h>
#include <cstdint>

#define N_NODES 50000
#define N_EDGES 625000
#define IN_DIM  512
#define HID     128
#define OUT_DIM 40
#define N_LAYERS 3
#define NB_SCAN ((N_NODES + 1023) / 1024)
#define N_TILES ((N_NODES + 127) / 128)

// ---------------- scratch ---------------------------------------------------
__device__ float g_h[N_NODES * HID];
__device__ float g_z[N_NODES * HID];
__device__ int   g_deg[N_NODES];
__device__ int   g_off[N_NODES];
__device__ int   g_cur[N_NODES];
__device__ uint2 g_edge[N_EDGES];          // {src, w_bits}
__device__ int   g_bsum[64];
__device__ uint32_t g_eBh[HID * (IN_DIM / 2)];
__device__ uint32_t g_eBl[HID * (IN_DIM / 2)];
__device__ uint32_t g_W1h[N_LAYERS * HID * (HID / 2)];
__device__ uint32_t g_W1l[N_LAYERS * HID * (HID / 2)];
__device__ uint32_t g_W2h[N_LAYERS * HID * (HID / 2)];
__device__ uint32_t g_W2l[N_LAYERS * HID * (HID / 2)];

// ---------------- helpers ----------------------------------------------------
__device__ __forceinline__ uint32_t smem_u32(const void* p) {
    uint32_t a;
    asm("{ .reg .u64 t; cvta.to.shared.u64 t, %1; cvt.u32.u64 %0, t; }" : "=r"(a) : "l"(p));
    return a;
}
__device__ __forceinline__ void split2(float v0, float v1, uint32_t& hi, uint32_t& lo) {
    uint16_t h0, h1, l0, l1;
    asm("cvt.rn.bf16.f32 %0, %1;" : "=h"(h0) : "f"(v0));
    asm("cvt.rn.bf16.f32 %0, %1;" : "=h"(h1) : "f"(v1));
    float r0 = v0 - __uint_as_float((uint32_t)h0 << 16);
    float r1 = v1 - __uint_as_float((uint32_t)h1 << 16);
    asm("cvt.rn.bf16.f32 %0, %1;" : "=h"(l0) : "f"(r0));
    asm("cvt.rn.bf16.f32 %0, %1;" : "=h"(l1) : "f"(r1));
    hi = ((uint32_t)h1 << 16) | h0;
    lo = ((uint32_t)l1 << 16) | l0;
}
__device__ __forceinline__ void mma_bf16(float* c, uint32_t a0, uint32_t a1,
                                         uint32_t a2, uint32_t a3,
                                         uint32_t b0, uint32_t b1) {
    asm volatile("mma.sync.aligned.m16n8k16.row.col.f32.bf16.bf16.f32 "
                 "{%0,%1,%2,%3}, {%4,%5,%6,%7}, {%8,%9}, {%0,%1,%2,%3};"
                 : "+f"(c[0]), "+f"(c[1]), "+f"(c[2]), "+f"(c[3])
                 : "r"(a0), "r"(a1), "r"(a2), "r"(a3), "r"(b0), "r"(b1));
}
__device__ __forceinline__ void ldsm_x4(uint32_t& r0, uint32_t& r1, uint32_t& r2,
                                        uint32_t& r3, uint32_t addr) {
    asm volatile("ldmatrix.sync.aligned.m8n8.x4.shared.b16 {%0,%1,%2,%3}, [%4];"
                 : "=r"(r0), "=r"(r1), "=r"(r2), "=r"(r3) : "r"(addr));
}

// ---------------- CSR build -------------------------------------------------
__global__ void zero_deg_kernel() {
    int i = blockIdx.x * blockDim.x + threadIdx.x;
    if (i < N_NODES) g_deg[i] = 0;
}
__global__ void hist_kernel(const int* __restrict__ dst) {
    int e = blockIdx.x * blockDim.x + threadIdx.x;
    if (e < N_EDGES) atomicAdd(&g_deg[dst[e]], 1);
}
__global__ void scan1_kernel() {
    __shared__ int s[1024];
    int t = threadIdx.x;
    int i = blockIdx.x * 1024 + t;
    int v = (i < N_NODES) ? g_deg[i] : 0;
    s[t] = v;
    __syncthreads();
    for (int d = 1; d < 1024; d <<= 1) {
        int tmp = (t >= d) ? s[t - d] : 0;
        __syncthreads();
        s[t] += tmp;
        __syncthreads();
    }
    if (i < N_NODES) g_off[i] = s[t] - v;
    if (t == 1023) g_bsum[blockIdx.x] = s[1023];
}
__global__ void scan23_kernel() {
    __shared__ int red[64];
    __shared__ int base_s;
    int t = threadIdx.x;
    if (t < 64) red[t] = (t < NB_SCAN && t < (int)blockIdx.x) ? g_bsum[t] : 0;
    __syncthreads();
    if (t < 32) {
        int s = red[t] + red[t + 32];
        for (int d = 16; d > 0; d >>= 1) s += __shfl_down_sync(0xffffffffu, s, d);
        if (t == 0) base_s = s;
    }
    __syncthreads();
    int i = blockIdx.x * 1024 + t;
    if (i < N_NODES) {
        int o = g_off[i] + base_s;
        g_off[i] = o;
        g_cur[i] = o;
    }
}
__global__ void scatter_kernel(const int* __restrict__ src,
                               const int* __restrict__ dst,
                               const float* __restrict__ ew) {
    int e = blockIdx.x * blockDim.x + threadIdx.x;
    if (e < N_EDGES) {
        int d = dst[e];
        int pos = atomicAdd(&g_cur[d], 1);
        g_edge[pos] = make_uint2((uint32_t)src[e], __float_as_uint(ew[e]));
    }
}

// ---------------- weight prep ------------------------------------------------
__global__ void prep_emb_kernel(const float* __restrict__ W) {
    int idx = blockIdx.x * blockDim.x + threadIdx.x;
    int n = idx >> 8, k2 = idx & 255;
    uint32_t hi, lo;
    split2(W[(size_t)(2 * k2) * HID + n], W[(size_t)(2 * k2 + 1) * HID + n], hi, lo);
    g_eBh[n * 256 + k2] = hi;
    g_eBl[n * 256 + k2] = lo;
}
__global__ void prep_w_kernel(const float* __restrict__ W1, const float* __restrict__ W2) {
    int idx = blockIdx.x * blockDim.x + threadIdx.x;
    if (idx >= N_LAYERS * HID * 64) return;
    int l = idx / (HID * 64);
    int rem = idx - l * HID * 64;
    int n = rem >> 6, k2 = rem & 63;
    const float* w1 = W1 + (size_t)l * HID * HID;
    const float* w2 = W2 + (size_t)l * HID * HID;
    uint32_t hi, lo;
    split2(w1[(2 * k2) * HID + n], w1[(2 * k2 + 1) * HID + n], hi, lo);
    g_W1h[idx] = hi; g_W1l[idx] = lo;
    split2(w2[(2 * k2) * HID + n], w2[(2 * k2 + 1) * HID + n], hi, lo);
    g_W2h[idx] = hi; g_W2l[idx] = lo;
}

// ---------------- emb GEMM: double-buffered k-loop --------------------------
#define ST 36
#define CHW (128 * ST)              // words per array
#define BUFW (4 * CHW)              // words per stage buffer
__global__ void __launch_bounds__(512, 1)
emb_gemm_kernel(const float* __restrict__ A, const float* __restrict__ bias, int M) {
    extern __shared__ uint32_t sh[];

    const int tid = threadIdx.x, lane = tid & 31, wid = tid >> 5;
    const int g = lane >> 2, tg = lane & 3;
    const int wm = wid & 7, wn = wid >> 3;     // 8 x 2 warps, 16x64 tiles
    const int row0 = blockIdx.x * 128;

    const int lr = lane & 7, lo8 = (lane >> 3) & 1, hi16 = (lane >> 4) & 1;
    const uint32_t shB = smem_u32(sh);
    const int aRowOff = (wm * 16 + lr + 8 * lo8) * ST + 4 * hi16;   // words
    const int bRowOff = (wn * 64 + lr + 8 * hi16) * ST + 4 * lo8;   // words

    float4 aR[4];
    uint4  bRh[2], bRl[2];

    // prologue: load chunk 0
#pragma unroll
    for (int it = 0; it < 4; it++) {
        int e = tid + it * 512;
        int m = e >> 4, j = e & 15;
        int r = row0 + m;
        aR[it] = make_float4(0.f, 0.f, 0.f, 0.f);
        if (r < M) aR[it] = *(const float4*)(A + (size_t)r * IN_DIM + j * 4);
    }
#pragma unroll
    for (int it = 0; it < 2; it++) {
        int e = tid + it * 512;
        int n = e >> 3, q = e & 7;
        bRh[it] = *(const uint4*)(g_eBh + n * 256 + q * 4);
        bRl[it] = *(const uint4*)(g_eBl + n * 256 + q * 4);
    }
    // store chunk 0 into buffer 0
    {
        uint32_t* Ah = sh;            uint32_t* Al = sh + CHW;
        uint32_t* Bh = sh + 2 * CHW;  uint32_t* Bl = sh + 3 * CHW;
#pragma unroll
        for (int it = 0; it < 4; it++) {
            int e = tid + it * 512;
            int m = e >> 4, j = e & 15;
            uint32_t h0, l0, h1, l1;
            split2(aR[it].x, aR[it].y, h0, l0);
            split2(aR[it].z, aR[it].w, h1, l1);
            int o = m * ST + j * 2;
            Ah[o] = h0; Ah[o + 1] = h1;
            Al[o] = l0; Al[o + 1] = l1;
        }
#pragma unroll
        for (int it = 0; it < 2; it++) {
            int e = tid + it * 512;
            int n = e >> 3, q = e & 7;
            int o = n * ST + q * 4;
            *(uint4*)(Bh + o) = bRh[it];
            *(uint4*)(Bl + o) = bRl[it];
        }
    }
    __syncthreads();

    float c[8][4];
#pragma unroll
    for (int ni = 0; ni < 8; ni++)
#pragma unroll
        for (int q = 0; q < 4; q++) c[ni][q] = 0.f;

    const int NCH = IN_DIM / 64;   // 8 chunks
    for (int ci = 0; ci < NCH; ci++) {
        const int p = ci & 1;
        const uint32_t base = shB + (uint32_t)p * BUFW * 4u;
        const uint32_t AhB = base, AlB = base + CHW * 4u;
        const uint32_t BhB = base + 2u * CHW * 4u, BlB = base + 3u * CHW * 4u;

        // issue LDGs for next chunk (latency hidden by MMA below)
        if (ci + 1 < NCH) {
            int kn = (ci + 1) * 64, kn2 = kn >> 1;
#pragma unroll
            for (int it = 0; it < 4; it++) {
                int e = tid + it * 512;
                int m = e >> 4, j = e & 15;
                int r = row0 + m;
                aR[it] = make_float4(0.f, 0.f, 0.f, 0.f);
                if (r < M) aR[it] = *(const float4*)(A + (size_t)r * IN_DIM + kn + j * 4);
            }
#pragma unroll
            for (int it = 0; it < 2; it++) {
                int e = tid + it * 512;
                int n = e >> 3, q = e & 7;
                bRh[it] = *(const uint4*)(g_eBh + n * 256 + kn2 + q * 4);
                bRl[it] = *(const uint4*)(g_eBl + n * 256 + kn2 + q * 4);
            }
        }

        // MMA on buffer p
#pragma unroll
        for (int ks2 = 0; ks2 < 32; ks2 += 8) {
            uint32_t a0, a1, a2, a3, l0, l1, l2, l3;
            ldsm_x4(a0, a1, a2, a3, AhB + (uint32_t)(aRowOff + ks2) * 4u);
            ldsm_x4(l0, l1, l2, l3, AlB + (uint32_t)(aRowOff + ks2) * 4u);
            uint32_t bh[8][2], bl[8][2];
#pragma unroll
            for (int q = 0; q < 4; q++) {
                uint32_t r0, r1, r2, r3;
                ldsm_x4(r0, r1, r2, r3, BhB + (uint32_t)(bRowOff + q * 16 * ST + ks2) * 4u);
                bh[2 * q][0] = r0; bh[2 * q][1] = r1;
                bh[2 * q + 1][0] = r2; bh[2 * q + 1][1] = r3;
                ldsm_x4(r0, r1, r2, r3, BlB + (uint32_t)(bRowOff + q * 16 * ST + ks2) * 4u);
                bl[2 * q][0] = r0; bl[2 * q][1] = r1;
                bl[2 * q + 1][0] = r2; bl[2 * q + 1][1] = r3;
            }
#pragma unroll
            for (int ni = 0; ni < 8; ni++) {
                mma_bf16(c[ni], a0, a1, a2, a3, bh[ni][0], bh[ni][1]);
                mma_bf16(c[ni], a0, a1, a2, a3, bl[ni][0], bl[ni][1]);
                mma_bf16(c[ni], l0, l1, l2, l3, bh[ni][0], bh[ni][1]);
            }
        }

        // store next chunk into buffer p^1
        if (ci + 1 < NCH) {
            uint32_t* Ah = sh + (p ^ 1) * BUFW;
            uint32_t* Al = Ah + CHW;
            uint32_t* Bh = Ah + 2 * CHW;
            uint32_t* Bl = Ah + 3 * CHW;
#pragma unroll
            for (int it = 0; it < 4; it++) {
                int e = tid + it * 512;
                int m = e >> 4, j = e & 15;
                uint32_t h0, l0, h1, l1;
                split2(aR[it].x, aR[it].y, h0, l0);
                split2(aR[it].z, aR[it].w, h1, l1);
                int o = m * ST + j * 2;
                Ah[o] = h0; Ah[o + 1] = h1;
                Al[o] = l0; Al[o + 1] = l1;
            }
#pragma unroll
            for (int it = 0; it < 2; it++) {
                int e = tid + it * 512;
                int n = e >> 3, q = e & 7;
                int o = n * ST + q * 4;
                *(uint4*)(Bh + o) = bRh[it];
                *(uint4*)(Bl + o) = bRl[it];
            }
            __syncthreads();
        }
    }

#pragma unroll
    for (int half = 0; half < 2; half++) {
        int row = row0 + wm * 16 + g + half * 8;
        if (row >= M) continue;
#pragma unroll
        for (int ni = 0; ni < 8; ni++) {
            int col = wn * 64 + ni * 8 + tg * 2;
            float2 o;
            o.x = c[ni][half * 2 + 0] + bias[col];
            o.y = c[ni][half * 2 + 1] + bias[col + 1];
            *(float2*)(g_h + (size_t)row * HID + col) = o;
        }
    }
}

// ---------------- persistent fused MLP (unchanged from R8) ------------------
#define ST2 68
__global__ void __launch_bounds__(512, 1)
mlp_fused_kernel(const uint32_t* __restrict__ W1h, const uint32_t* __restrict__ W1l,
                 const uint32_t* __restrict__ W2h, const uint32_t* __restrict__ W2l,
                 const float* __restrict__ b1, const float* __restrict__ b2, int M) {
    extern __shared__ uint32_t sh[];
    uint32_t* Ah  = sh;
    uint32_t* Al  = sh + 128 * ST2;
    uint32_t* Wh1 = sh + 2 * 128 * ST2;
    uint32_t* Wl1 = sh + 3 * 128 * ST2;
    uint32_t* Wh2 = sh + 4 * 128 * ST2;
    uint32_t* Wl2 = sh + 5 * 128 * ST2;

    const int tid = threadIdx.x, lane = tid & 31, wid = tid >> 5;
    const int g = lane >> 2, tg = lane & 3;
    const int wm = wid & 7, wn = wid >> 3;

    const int lr = lane & 7, lo8 = (lane >> 3) & 1, hi16 = (lane >> 4) & 1;
    const uint32_t AhB  = smem_u32(Ah),  AlB  = smem_u32(Al);
    const uint32_t Wh1B = smem_u32(Wh1), Wl1B = smem_u32(Wl1);
    const uint32_t Wh2B = smem_u32(Wh2), Wl2B = smem_u32(Wl2);
    const int aRowOff = (wm * 16 + lr + 8 * lo8) * ST2 + 4 * hi16;
    const int bRowOff = (wn * 64 + lr + 8 * hi16) * ST2 + 4 * lo8;

#pragma unroll
    for (int it = 0; it < 4; it++) {
        int e = tid + it * 512;
        int n = e >> 4, q = e & 15;
        int o = n * ST2 + q * 4;
        *(uint4*)(Wh1 + o) = *(const uint4*)(W1h + n * 64 + q * 4);
        *(uint4*)(Wl1 + o) = *(const uint4*)(W1l + n * 64 + q * 4);
        *(uint4*)(Wh2 + o) = *(const uint4*)(W2h + n * 64 + q * 4);
        *(uint4*)(Wl2 + o) = *(const uint4*)(W2l + n * 64 + q * 4);
    }

    for (int tile = blockIdx.x; tile < N_TILES; tile += gridDim.x) {
        const int row0 = tile * 128;
        __syncthreads();
#pragma unroll
        for (int it = 0; it < 8; it++) {
            int e = tid + it * 512;
            int m = e >> 5, j = e & 31;
            int r = row0 + m;
            float4 v = make_float4(0.f, 0.f, 0.f, 0.f);
            if (r < M) v = *(const float4*)(g_z + (size_t)r * HID + j * 4);
            uint32_t h0, l0, h1, l1;
            split2(v.x, v.y, h0, l0);
            split2(v.z, v.w, h1, l1);
            int o = m * ST2 + j * 2;
            Ah[o] = h0; Ah[o + 1] = h1;
            Al[o] = l0; Al[o + 1] = l1;
        }
        __syncthreads();

        float c[8][4];
#pragma unroll
        for (int ni = 0; ni < 8; ni++)
#pragma unroll
            for (int q = 0; q < 4; q++) c[ni][q] = 0.f;

        // GEMM1
#pragma unroll
        for (int ks2 = 0; ks2 < 64; ks2 += 8) {
            uint32_t a0, a1, a2, a3, l0, l1, l2, l3;
            ldsm_x4(a0, a1, a2, a3, AhB + (uint32_t)(aRowOff + ks2) * 4u);
            ldsm_x4(l0, l1, l2, l3, AlB + (uint32_t)(aRowOff + ks2) * 4u);
            uint32_t bh[8][2], bl[8][2];
#pragma unroll
            for (int q = 0; q < 4; q++) {
                uint32_t r0, r1, r2, r3;
                ldsm_x4(r0, r1, r2, r3, Wh1B + (uint32_t)(bRowOff + q * 16 * ST2 + ks2) * 4u);
                bh[2 * q][0] = r0; bh[2 * q][1] = r1;
                bh[2 * q + 1][0] = r2; bh[2 * q + 1][1] = r3;
                ldsm_x4(r0, r1, r2, r3, Wl1B + (uint32_t)(bRowOff + q * 16 * ST2 + ks2) * 4u);
                bl[2 * q][0] = r0; bl[2 * q][1] = r1;
                bl[2 * q + 1][0] = r2; bl[2 * q + 1][1] = r3;
            }
#pragma unroll
            for (int ni = 0; ni < 8; ni++) {
                mma_bf16(c[ni], a0, a1, a2, a3, bh[ni][0], bh[ni][1]);
                mma_bf16(c[ni], a0, a1, a2, a3, bl[ni][0], bl[ni][1]);
                mma_bf16(c[ni], l0, l1, l2, l3, bh[ni][0], bh[ni][1]);
            }
        }
        __syncthreads();

        // relu(c + b1) -> split -> Ah/Al
#pragma unroll
        for (int ni = 0; ni < 8; ni++) {
            int col = wn * 64 + ni * 8 + tg * 2;
            float bb0 = b1[col], bb1 = b1[col + 1];
            int k2 = wn * 32 + ni * 4 + tg;
            int r0 = wm * 16 + g;
            uint32_t hi, lo;
            split2(fmaxf(c[ni][0] + bb0, 0.f), fmaxf(c[ni][1] + bb1, 0.f), hi, lo);
            Ah[r0 * ST2 + k2] = hi; Al[r0 * ST2 + k2] = lo;
            split2(fmaxf(c[ni][2] + bb0, 0.f), fmaxf(c[ni][3] + bb1, 0.f), hi, lo);
            Ah[(r0 + 8) * ST2 + k2] = hi; Al[(r0 + 8) * ST2 + k2] = lo;
        }
        __syncthreads();

#pragma unroll
        for (int ni = 0; ni < 8; ni++)
#pragma unroll
            for (int q = 0; q < 4; q++) c[ni][q] = 0.f;

        // GEMM2
#pragma unroll
        for (int ks2 = 0; ks2 < 64; ks2 += 8) {
            uint32_t a0, a1, a2, a3, l0, l1, l2, l3;
            ldsm_x4(a0, a1, a2, a3, AhB + (uint32_t)(aRowOff + ks2) * 4u);
            ldsm_x4(l0, l1, l2, l3, AlB + (uint32_t)(aRowOff + ks2) * 4u);
            uint32_t bh[8][2], bl[8][2];
#pragma unroll
            for (int q = 0; q < 4; q++) {
                uint32_t r0, r1, r2, r3;
                ldsm_x4(r0, r1, r2, r3, Wh2B + (uint32_t)(bRowOff + q * 16 * ST2 + ks2) * 4u);
                bh[2 * q][0] = r0; bh[2 * q][1] = r1;
                bh[2 * q + 1][0] = r2; bh[2 * q + 1][1] = r3;
                ldsm_x4(r0, r1, r2, r3, Wl2B + (uint32_t)(bRowOff + q * 16 * ST2 + ks2) * 4u);
                bl[2 * q][0] = r0; bl[2 * q][1] = r1;
                bl[2 * q + 1][0] = r2; bl[2 * q + 1][1] = r3;
            }
#pragma unroll
            for (int ni = 0; ni < 8; ni++) {
                mma_bf16(c[ni], a0, a1, a2, a3, bh[ni][0], bh[ni][1]);
                mma_bf16(c[ni], a0, a1, a2, a3, bl[ni][0], bl[ni][1]);
                mma_bf16(c[ni], l0, l1, l2, l3, bh[ni][0], bh[ni][1]);
            }
        }

#pragma unroll
        for (int half = 0; half < 2; half++) {
            int row = row0 + wm * 16 + g + half * 8;
            if (row >= M) continue;
#pragma unroll
            for (int ni = 0; ni < 8; ni++) {
                int col = wn * 64 + ni * 8 + tg * 2;
                float2 o;
                o.x = fmaxf(c[ni][half * 2 + 0] + b2[col], 0.f);
                o.y = fmaxf(c[ni][half * 2 + 1] + b2[col + 1], 0.f);
                *(float2*)(g_h + (size_t)row * HID + col) = o;
            }
        }
    }
}

// ---------------- aggregation ------------------------------------------------
__global__ void agg_kernel() {
    int node = (blockIdx.x * blockDim.x + threadIdx.x) >> 5;
    int lane = threadIdx.x & 31;
    if (node >= N_NODES) return;
    int s = g_off[node];
    int d = g_deg[node];
    float4 acc = *(const float4*)(g_h + (size_t)node * HID + lane * 4);
    int i = 0;
    for (; i + 2 <= d; i += 2) {
        uint2 e0 = g_edge[s + i];
        uint2 e1 = g_edge[s + i + 1];
        float w0 = __uint_as_float(e0.y);
        float w1 = __uint_as_float(e1.y);
        float4 h0 = *(const float4*)(g_h + (size_t)e0.x * HID + lane * 4);
        float4 h1 = *(const float4*)(g_h + (size_t)e1.x * HID + lane * 4);
        acc.x += w0 * h0.x + w1 * h1.x;
        acc.y += w0 * h0.y + w1 * h1.y;
        acc.z += w0 * h0.z + w1 * h1.z;
        acc.w += w0 * h0.w + w1 * h1.w;
    }
    if (i < d) {
        uint2 e0 = g_edge[s + i];
        float w0 = __uint_as_float(e0.y);
        float4 h0 = *(const float4*)(g_h + (size_t)e0.x * HID + lane * 4);
        acc.x += w0 * h0.x; acc.y += w0 * h0.y;
        acc.z += w0 * h0.z; acc.w += w0 * h0.w;
    }
    *(float4*)(g_z + (size_t)node * HID + lane * 4) = acc;
}

// ---------------- readout ----------------------------------------------------
__global__ void readout_kernel(const float* __restrict__ Wr,
                               const float* __restrict__ br,
                               float* __restrict__ out, int M) {
    extern __shared__ float sm[];
    float* hs = sm;
    float* wt = sm + 128 * 132;
    const int row0 = blockIdx.x * 128;
    const int tr = threadIdx.x >> 3;
    const int cg = threadIdx.x & 7;

    for (int e = threadIdx.x; e < 128 * 128; e += 256) {
        int m = e >> 7, k = e & 127;
        int r = row0 + m;
        hs[m * 132 + k] = (r < M) ? g_h[(size_t)r * HID + k] : 0.f;
    }
    for (int e = threadIdx.x; e < 128 * OUT_DIM; e += 256) {
        int k = e / OUT_DIM, c = e % OUT_DIM;
        wt[c * 132 + k] = Wr[e];
    }
    __syncthreads();

    float acc[4][5];
#pragma unroll
    for (int r = 0; r < 4; r++)
#pragma unroll
        for (int c = 0; c < 5; c++) acc[r][c] = 0.f;

    for (int k = 0; k < 128; k += 4) {
        float4 hv[4];
#pragma unroll
        for (int r = 0; r < 4; r++)
            hv[r] = *(const float4*)(hs + (tr * 4 + r) * 132 + k);
#pragma unroll
        for (int c = 0; c < 5; c++) {
            float4 wv = *(const float4*)(wt + (cg * 5 + c) * 132 + k);
#pragma unroll
            for (int r = 0; r < 4; r++)
                acc[r][c] += hv[r].x * wv.x + hv[r].y * wv.y
                           + hv[r].z * wv.z + hv[r].w * wv.w;
        }
    }
#pragma unroll
    for (int r = 0; r < 4; r++) {
        int row = row0 + tr * 4 + r;
        if (row < M) {
#pragma unroll
            for (int c = 0; c < 5; c++) {
                int col = cg * 5 + c;
                out[(size_t)row * OUT_DIM + col] = acc[r][c] + br[col];
            }
        }
    }
}

// ---------------- launch ----------------------------------------------------
extern "C" void kernel_launch(void* const* d_in, const int* in_sizes, int n_in,
                              void* d_out, int out_size) {
    const float* features = (const float*)d_in[0];
    const int*   src      = (const int*)  d_in[1];
    const int*   dst      = (const int*)  d_in[2];
    const float* edge_w   = (const float*)d_in[3];
    const float* emb_W    = (const float*)d_in[4];
    const float* emb_b    = (const float*)d_in[5];
    const float* W1       = (const float*)d_in[6];
    const float* b1       = (const float*)d_in[7];
    const float* W2       = (const float*)d_in[8];
    const float* b2       = (const float*)d_in[9];
    const float* ro_W     = (const float*)d_in[10];
    const float* ro_b     = (const float*)d_in[11];
    float* out = (float*)d_out;

    const int emb_smem = 2 * 4 * 128 * ST * (int)sizeof(uint32_t);   // 147456
    const int mlp_smem = 6 * 128 * ST2 * (int)sizeof(uint32_t);
    const int ro_smem  = (128 * 132 + OUT_DIM * 132) * (int)sizeof(float);
    cudaFuncSetAttribute(emb_gemm_kernel,  cudaFuncAttributeMaxDynamicSharedMemorySize, emb_smem);
    cudaFuncSetAttribute(mlp_fused_kernel, cudaFuncAttributeMaxDynamicSharedMemorySize, mlp_smem);
    cudaFuncSetAttribute(readout_kernel,   cudaFuncAttributeMaxDynamicSharedMemorySize, ro_smem);

    uint32_t *d_W1h, *d_W1l, *d_W2h, *d_W2l;
    cudaGetSymbolAddress((void**)&d_W1h, g_W1h);
    cudaGetSymbolAddress((void**)&d_W1l, g_W1l);
    cudaGetSymbolAddress((void**)&d_W2h, g_W2h);
    cudaGetSymbolAddress((void**)&d_W2l, g_W2l);

    cudaStream_t side = cudaStreamPerThread;
    cudaEvent_t evA, evB;
    cudaEventCreateWithFlags(&evA, cudaEventDisableTiming);
    cudaEventCreateWithFlags(&evB, cudaEventDisableTiming);

    cudaEventRecord(evA, 0);
    cudaStreamWaitEvent(side, evA, 0);

    prep_emb_kernel<<<HID * 256 / 256, 256>>>(emb_W);                         // main #0
    prep_w_kernel<<<(N_LAYERS * HID * 64 + 255) / 256, 256>>>(W1, W2);        // main #1
    zero_deg_kernel<<<(N_NODES + 255) / 256, 256, 0, side>>>();               // side #2
    emb_gemm_kernel<<<N_TILES, 512, emb_smem>>>(features, emb_b, N_NODES);    // main #3 <- profiled
    hist_kernel<<<(N_EDGES + 255) / 256, 256, 0, side>>>(dst);
    scan1_kernel<<<NB_SCAN, 1024, 0, side>>>();
    scan23_kernel<<<NB_SCAN, 1024, 0, side>>>();
    scatter_kernel<<<(N_EDGES + 255) / 256, 256, 0, side>>>(src, dst, edge_w);

    cudaEventRecord(evB, side);
    cudaStreamWaitEvent(0, evB, 0);

    const int agg_blocks = (N_NODES * 32 + 255) / 256;
    for (int l = 0; l < N_LAYERS; l++) {
        agg_kernel<<<agg_blocks, 256>>>();
        mlp_fused_kernel<<<148, 512, mlp_smem>>>(
            d_W1h + (size_t)l * HID * 64, d_W1l + (size_t)l * HID * 64,
            d_W2h + (size_t)l * HID * 64, d_W2l + (size_t)l * HID * 64,
            b1 + (size_t)l * HID, b2 + (size_t)l * HID, N_NODES);
    }
    readout_kernel<<<N_TILES, 256, ro_smem>>>(ro_W, ro_b, out, N_NODES);
}